// round 1
// baseline (speedup 1.0000x reference)
#include <cuda_runtime.h>
#include <cuda_bf16.h>
#include <math.h>

#define NN_NODES 100000
#define EE_EDGES 3200000
#define FDIM 256
#define CDIM 64
#define LN_EPS 1e-5

// ---------------- scratch (static device globals; no allocation) ----------------
__device__ int    g_deg_s[NN_NODES];
__device__ int    g_deg_d[NN_NODES];
__device__ float  g_norm_s[NN_NODES];
__device__ float  g_norm_d[NN_NODES];
__device__ int    g_row_off[NN_NODES + 1];
__device__ int    g_cursor[NN_NODES];
__device__ int    g_col[EE_EDGES];
__device__ float  g_agg[(size_t)NN_NODES * FDIM];
__device__ float  g_h[(size_t)NN_NODES * FDIM];
__device__ double g_stats[2];   // sum, sumsq
__device__ float  g_ln[2];      // mu, inv_std

// ---------------- setup kernels ----------------
__global__ void k_init() {
    int i = blockIdx.x * blockDim.x + threadIdx.x;
    if (i < NN_NODES) { g_deg_s[i] = 0; g_deg_d[i] = 0; }
    if (i == 0) { g_stats[0] = 0.0; g_stats[1] = 0.0; }
}

__global__ void k_degrees(const int* __restrict__ src, const int* __restrict__ dst) {
    int e = blockIdx.x * blockDim.x + threadIdx.x;
    if (e < EE_EDGES) {
        atomicAdd(&g_deg_s[src[e]], 1);
        atomicAdd(&g_deg_d[dst[e]], 1);
    }
}

// single-block scan: row offsets (by dst) + cursors + norms
__global__ void k_scan() {
    const int T = 1024;
    int t = threadIdx.x;
    const int chunk = (NN_NODES + T - 1) / T;
    int beg = t * chunk;
    int end = min(beg + chunk, NN_NODES);
    int local = 0;
    for (int i = beg; i < end; i++) local += g_deg_d[i];

    __shared__ int sh[T];
    sh[t] = local;
    __syncthreads();
    for (int off = 1; off < T; off <<= 1) {
        int v = (t >= off) ? sh[t - off] : 0;
        __syncthreads();
        sh[t] += v;
        __syncthreads();
    }
    int run = sh[t] - local;   // exclusive prefix at beg
    for (int i = beg; i < end; i++) {
        g_row_off[i] = run;
        g_cursor[i] = run;
        run += g_deg_d[i];
    }
    if (t == T - 1) g_row_off[NN_NODES] = sh[T - 1];

    for (int i = beg; i < end; i++) {
        g_norm_s[i] = rsqrtf((float)max(g_deg_s[i], 1));
        g_norm_d[i] = rsqrtf((float)max(g_deg_d[i], 1));
    }
}

__global__ void k_fill(const int* __restrict__ src, const int* __restrict__ dst) {
    int e = blockIdx.x * blockDim.x + threadIdx.x;
    if (e < EE_EDGES) {
        int p = atomicAdd(&g_cursor[dst[e]], 1);
        g_col[p] = src[e];
    }
}

// ---------------- SpMM: pull (warp per dst row), 256-wide features ----------------
// out[i][:] = norm_d[i] * sum_{j in N(i)} norm_s[j] * LN(h[j][:])
template <bool LN>
__global__ void k_spmm256(const float* __restrict__ hin, float* __restrict__ out) {
    int gw = (blockIdx.x * blockDim.x + threadIdx.x) >> 5;
    int lane = threadIdx.x & 31;
    if (gw >= NN_NODES) return;

    float mu = 0.f, inv = 1.f;
    if (LN) { mu = g_ln[0]; inv = g_ln[1]; }

    int s0 = g_row_off[gw], s1 = g_row_off[gw + 1];
    float4 a0 = make_float4(0.f, 0.f, 0.f, 0.f);
    float4 a1 = make_float4(0.f, 0.f, 0.f, 0.f);
    const float4* __restrict__ h4 = reinterpret_cast<const float4*>(hin);

    for (int base = s0; base < s1; base += 32) {
        int kk = base + lane;
        int j = 0; float sc = 0.f;
        if (kk < s1) { j = g_col[kk]; sc = g_norm_s[j]; }
        int cnt = min(32, s1 - base);
#pragma unroll 4
        for (int i = 0; i < cnt; i++) {
            int   jj = __shfl_sync(0xffffffffu, j, i);
            float sj = __shfl_sync(0xffffffffu, sc, i);
            const float4* r = h4 + (size_t)jj * (FDIM / 4);
            float4 v0 = r[lane];
            float4 v1 = r[lane + 32];
            float sv = LN ? (sj * inv) : sj;
            if (LN) {
                a0.x = fmaf(v0.x - mu, sv, a0.x); a0.y = fmaf(v0.y - mu, sv, a0.y);
                a0.z = fmaf(v0.z - mu, sv, a0.z); a0.w = fmaf(v0.w - mu, sv, a0.w);
                a1.x = fmaf(v1.x - mu, sv, a1.x); a1.y = fmaf(v1.y - mu, sv, a1.y);
                a1.z = fmaf(v1.z - mu, sv, a1.z); a1.w = fmaf(v1.w - mu, sv, a1.w);
            } else {
                a0.x = fmaf(v0.x, sv, a0.x); a0.y = fmaf(v0.y, sv, a0.y);
                a0.z = fmaf(v0.z, sv, a0.z); a0.w = fmaf(v0.w, sv, a0.w);
                a1.x = fmaf(v1.x, sv, a1.x); a1.y = fmaf(v1.y, sv, a1.y);
                a1.z = fmaf(v1.z, sv, a1.z); a1.w = fmaf(v1.w, sv, a1.w);
            }
        }
    }
    float nd = g_norm_d[gw];
    a0.x *= nd; a0.y *= nd; a0.z *= nd; a0.w *= nd;
    a1.x *= nd; a1.y *= nd; a1.z *= nd; a1.w *= nd;
    float4* o4 = reinterpret_cast<float4*>(out);
    o4[(size_t)gw * (FDIM / 4) + lane]      = a0;
    o4[(size_t)gw * (FDIM / 4) + 32 + lane] = a1;
}

// ---------------- SpMM 64-wide (final layer, with bias) ----------------
__global__ void k_spmm64(const float* __restrict__ tin, const float* __restrict__ bias,
                         float* __restrict__ out) {
    int gw = (blockIdx.x * blockDim.x + threadIdx.x) >> 5;
    int lane = threadIdx.x & 31;
    if (gw >= NN_NODES) return;

    int s0 = g_row_off[gw], s1 = g_row_off[gw + 1];
    float2 a = make_float2(0.f, 0.f);
    const float2* __restrict__ t2 = reinterpret_cast<const float2*>(tin);

    for (int base = s0; base < s1; base += 32) {
        int kk = base + lane;
        int j = 0; float sc = 0.f;
        if (kk < s1) { j = g_col[kk]; sc = g_norm_s[j]; }
        int cnt = min(32, s1 - base);
#pragma unroll 4
        for (int i = 0; i < cnt; i++) {
            int   jj = __shfl_sync(0xffffffffu, j, i);
            float sj = __shfl_sync(0xffffffffu, sc, i);
            float2 v = t2[(size_t)jj * (CDIM / 2) + lane];
            a.x = fmaf(v.x, sj, a.x);
            a.y = fmaf(v.y, sj, a.y);
        }
    }
    float nd = g_norm_d[gw];
    float2 b = reinterpret_cast<const float2*>(bias)[lane];
    float2 o;
    o.x = fmaf(a.x, nd, b.x);
    o.y = fmaf(a.y, nd, b.y);
    reinterpret_cast<float2*>(out)[(size_t)gw * (CDIM / 2) + lane] = o;
}

// ---------------- SGEMM (fp32, register-blocked), fused epilogue ----------------
// C[M,Nn] = op(A[M,K]) @ B[K,Nn]   (op = optional (a-mu)*inv elementwise)
// epilogue: optional +bias, relu, double sum/sumsq stats via atomics
template <int BM, int BN, int BK, int TM, int TN, bool BIAS_RELU, bool STATS, bool LNA>
__global__ void k_sgemm(const float* __restrict__ A, const float* __restrict__ B,
                        const float* __restrict__ bias, float* __restrict__ C,
                        int M, int Nn, int K) {
    __shared__ float As[BK * BM];
    __shared__ float Bs[BK * BN];

    const int tid = threadIdx.x;
    const int TX = BN / TN;              // 16
    const int tx = tid % TX;
    const int ty = tid / TX;
    const int bm0 = blockIdx.x * BM;
    const int bn0 = blockIdx.y * BN;

    float mu = 0.f, inv = 1.f;
    if (LNA) { mu = g_ln[0]; inv = g_ln[1]; }

    float acc[TM][TN];
#pragma unroll
    for (int i = 0; i < TM; i++)
#pragma unroll
        for (int j = 0; j < TN; j++) acc[i][j] = 0.f;

    // A: one float4 per thread per tile
    const int am = tid / (BK / 4);
    const int ac = tid % (BK / 4);
    const int grow = bm0 + am;
    constexpr int BLD = (BK * BN) / ((BM / TM) * (BN / TN));  // floats/thread for B

    for (int k0 = 0; k0 < K; k0 += BK) {
        float4 va = make_float4(0.f, 0.f, 0.f, 0.f);
        if (grow < M)
            va = *reinterpret_cast<const float4*>(&A[(size_t)grow * K + k0 + ac * 4]);
        if (LNA) {
            va.x = (va.x - mu) * inv; va.y = (va.y - mu) * inv;
            va.z = (va.z - mu) * inv; va.w = (va.w - mu) * inv;
        }
        As[(ac * 4 + 0) * BM + am] = va.x;
        As[(ac * 4 + 1) * BM + am] = va.y;
        As[(ac * 4 + 2) * BM + am] = va.z;
        As[(ac * 4 + 3) * BM + am] = va.w;

        if (BLD == 4) {
            int bk = tid / (BN / 4);
            int bn = tid % (BN / 4);
            float4 vb = *reinterpret_cast<const float4*>(&B[(size_t)(k0 + bk) * Nn + bn0 + bn * 4]);
            *reinterpret_cast<float4*>(&Bs[bk * BN + bn * 4]) = vb;
        } else {
            int bk = tid / (BN / 2);
            int bn = tid % (BN / 2);
            float2 vb = *reinterpret_cast<const float2*>(&B[(size_t)(k0 + bk) * Nn + bn0 + bn * 2]);
            *reinterpret_cast<float2*>(&Bs[bk * BN + bn * 2]) = vb;
        }
        __syncthreads();

#pragma unroll
        for (int kk = 0; kk < BK; kk++) {
            float ra[TM], rb[TN];
#pragma unroll
            for (int i = 0; i < TM; i++) ra[i] = As[kk * BM + ty * TM + i];
#pragma unroll
            for (int j = 0; j < TN; j++) rb[j] = Bs[kk * BN + tx * TN + j];
#pragma unroll
            for (int i = 0; i < TM; i++)
#pragma unroll
                for (int j = 0; j < TN; j++)
                    acc[i][j] = fmaf(ra[i], rb[j], acc[i][j]);
        }
        __syncthreads();
    }

    const int cg0 = bn0 + tx * TN;
    double psum = 0.0, psq = 0.0;
#pragma unroll
    for (int i = 0; i < TM; i++) {
        int row = bm0 + ty * TM + i;
        if (row >= M) continue;
#pragma unroll
        for (int j = 0; j < TN; j += 4) {
            float4 c;
            c.x = acc[i][j]; c.y = acc[i][j + 1]; c.z = acc[i][j + 2]; c.w = acc[i][j + 3];
            if (BIAS_RELU) {
                float4 bb = *reinterpret_cast<const float4*>(&bias[cg0 + j]);
                c.x = fmaxf(c.x + bb.x, 0.f); c.y = fmaxf(c.y + bb.y, 0.f);
                c.z = fmaxf(c.z + bb.z, 0.f); c.w = fmaxf(c.w + bb.w, 0.f);
            }
            *reinterpret_cast<float4*>(&C[(size_t)row * Nn + cg0 + j]) = c;
            if (STATS) {
                psum += (double)c.x + (double)c.y + (double)c.z + (double)c.w;
                psq  += (double)c.x * c.x + (double)c.y * c.y +
                        (double)c.z * c.z + (double)c.w * c.w;
            }
        }
    }

    if (STATS) {
#pragma unroll
        for (int off = 16; off > 0; off >>= 1) {
            psum += __shfl_down_sync(0xffffffffu, psum, off);
            psq  += __shfl_down_sync(0xffffffffu, psq, off);
        }
        if ((tid & 31) == 0) {
            atomicAdd(&g_stats[0], psum);
            atomicAdd(&g_stats[1], psq);
        }
    }
}

__global__ void k_finalize(double count) {
    double s = g_stats[0], ss = g_stats[1];
    double mu = s / count;
    double var = ss / count - mu * mu;
    g_ln[0] = (float)mu;
    g_ln[1] = (float)(1.0 / sqrt(var + (double)LN_EPS));
    g_stats[0] = 0.0;
    g_stats[1] = 0.0;
}

// ---------------- launch ----------------
extern "C" void kernel_launch(void* const* d_in, const int* in_sizes, int n_in,
                              void* d_out, int out_size) {
    const float* feat = (const float*)d_in[0];
    const int*   src  = (const int*)d_in[1];
    const int*   dst  = (const int*)d_in[2];
    const float* W0   = (const float*)d_in[3];
    const float* b0   = (const float*)d_in[4];
    const float* W1   = (const float*)d_in[5];
    const float* b1   = (const float*)d_in[6];
    const float* W2   = (const float*)d_in[7];
    const float* b2   = (const float*)d_in[8];
    float* out = (float*)d_out;

    float *agg = nullptr, *hbuf = nullptr;
    cudaGetSymbolAddress((void**)&agg, g_agg);
    cudaGetSymbolAddress((void**)&hbuf, g_h);

    const int NB_N = (NN_NODES + 255) / 256;
    const int NB_E = (EE_EDGES + 255) / 256;
    const int NB_W = (NN_NODES * 32 + 255) / 256;  // warp per row

    // setup: degrees, norms, CSR (by dst)
    k_init<<<NB_N, 256>>>();
    k_degrees<<<NB_E, 256>>>(src, dst);
    k_scan<<<1, 1024>>>();
    k_fill<<<NB_E, 256>>>(src, dst);

    const int GM = (NN_NODES + 127) / 128;
    const double cnt = (double)NN_NODES * FDIM;

    // layer 1: agg = DAD*X ; h1 = relu(agg@W0 + b0) (+stats)
    k_spmm256<false><<<NB_W, 256>>>(feat, agg);
    k_sgemm<128, 128, 8, 8, 8, true, true, false>
        <<<dim3(GM, FDIM / 128), 256>>>(agg, W0, b0, hbuf, NN_NODES, FDIM, FDIM);
    k_finalize<<<1, 1>>>(cnt);

    // layer 2: agg = DAD*LN(h1) ; h2 = relu(agg@W1 + b1) (+stats)
    k_spmm256<true><<<NB_W, 256>>>(hbuf, agg);
    k_sgemm<128, 128, 8, 8, 8, true, true, false>
        <<<dim3(GM, FDIM / 128), 256>>>(agg, W1, b1, hbuf, NN_NODES, FDIM, FDIM);
    k_finalize<<<1, 1>>>(cnt);

    // layer 3 (reordered): t = LN(h2)@W2 ; out = DAD*t + b2
    k_sgemm<128, 64, 8, 8, 4, false, false, true>
        <<<dim3(GM, 1), 256>>>(hbuf, W2, nullptr, agg, NN_NODES, CDIM, FDIM);
    k_spmm64<<<NB_W, 256>>>(agg, b2, out);
}

// round 2
// speedup vs baseline: 1.2854x; 1.2854x over previous
#include <cuda_runtime.h>
#include <cuda_bf16.h>
#include <math.h>

#define NN_NODES 100000
#define EE_EDGES 3200000
#define FDIM 256
#define CDIM 64
#define LN_EPS 1e-5

// ---------------- scratch (static device globals; no allocation) ----------------
__device__ int    g_deg_s[NN_NODES];
__device__ int    g_deg_d[NN_NODES];
__device__ float  g_norm_s[NN_NODES];
__device__ float  g_norm_d[NN_NODES];
__device__ int    g_row_off[NN_NODES + 1];
__device__ int    g_cursor[NN_NODES];
__device__ int    g_col[EE_EDGES];
__device__ float  g_agg[(size_t)NN_NODES * FDIM];
__device__ float  g_h[(size_t)NN_NODES * FDIM];
__device__ double g_stats[2];   // sum, sumsq
__device__ float  g_ln[2];      // mu, inv_std

// ---------------- setup kernels ----------------
__global__ void k_init() {
    int i = blockIdx.x * blockDim.x + threadIdx.x;
    if (i < NN_NODES) { g_deg_s[i] = 0; g_deg_d[i] = 0; }
    if (i == 0) { g_stats[0] = 0.0; g_stats[1] = 0.0; }
}

__global__ void k_degrees(const int* __restrict__ src, const int* __restrict__ dst) {
    int e = blockIdx.x * blockDim.x + threadIdx.x;
    if (e < EE_EDGES) {
        atomicAdd(&g_deg_s[src[e]], 1);
        atomicAdd(&g_deg_d[dst[e]], 1);
    }
}

// single-block scan: row offsets (by dst) + cursors + norms
__global__ void k_scan() {
    const int T = 1024;
    int t = threadIdx.x;
    const int chunk = (NN_NODES + T - 1) / T;
    int beg = t * chunk;
    int end = min(beg + chunk, NN_NODES);
    int local = 0;
    for (int i = beg; i < end; i++) local += g_deg_d[i];

    __shared__ int sh[T];
    sh[t] = local;
    __syncthreads();
    for (int off = 1; off < T; off <<= 1) {
        int v = (t >= off) ? sh[t - off] : 0;
        __syncthreads();
        sh[t] += v;
        __syncthreads();
    }
    int run = sh[t] - local;   // exclusive prefix at beg
    for (int i = beg; i < end; i++) {
        g_row_off[i] = run;
        g_cursor[i] = run;
        run += g_deg_d[i];
    }
    if (t == T - 1) g_row_off[NN_NODES] = sh[T - 1];

    for (int i = beg; i < end; i++) {
        g_norm_s[i] = rsqrtf((float)max(g_deg_s[i], 1));
        g_norm_d[i] = rsqrtf((float)max(g_deg_d[i], 1));
    }
}

__global__ void k_fill(const int* __restrict__ src, const int* __restrict__ dst) {
    int e = blockIdx.x * blockDim.x + threadIdx.x;
    if (e < EE_EDGES) {
        int p = atomicAdd(&g_cursor[dst[e]], 1);
        g_col[p] = src[e];
    }
}

// ---------------- SpMM: pull (warp per dst row), 256-wide features ----------------
template <bool LN>
__global__ void k_spmm256(const float* __restrict__ hin, float* __restrict__ out) {
    int gw = (blockIdx.x * blockDim.x + threadIdx.x) >> 5;
    int lane = threadIdx.x & 31;
    if (gw >= NN_NODES) return;

    float mu = 0.f, inv = 1.f;
    if (LN) { mu = g_ln[0]; inv = g_ln[1]; }

    int s0 = g_row_off[gw], s1 = g_row_off[gw + 1];
    float4 a0 = make_float4(0.f, 0.f, 0.f, 0.f);
    float4 a1 = make_float4(0.f, 0.f, 0.f, 0.f);
    const float4* __restrict__ h4 = reinterpret_cast<const float4*>(hin);

    for (int base = s0; base < s1; base += 32) {
        int kk = base + lane;
        int j = 0; float sc = 0.f;
        if (kk < s1) { j = g_col[kk]; sc = g_norm_s[j]; }
        int cnt = min(32, s1 - base);
#pragma unroll 4
        for (int i = 0; i < cnt; i++) {
            int   jj = __shfl_sync(0xffffffffu, j, i);
            float sj = __shfl_sync(0xffffffffu, sc, i);
            const float4* r = h4 + (size_t)jj * (FDIM / 4);
            float4 v0 = r[lane];
            float4 v1 = r[lane + 32];
            float sv = LN ? (sj * inv) : sj;
            if (LN) {
                a0.x = fmaf(v0.x - mu, sv, a0.x); a0.y = fmaf(v0.y - mu, sv, a0.y);
                a0.z = fmaf(v0.z - mu, sv, a0.z); a0.w = fmaf(v0.w - mu, sv, a0.w);
                a1.x = fmaf(v1.x - mu, sv, a1.x); a1.y = fmaf(v1.y - mu, sv, a1.y);
                a1.z = fmaf(v1.z - mu, sv, a1.z); a1.w = fmaf(v1.w - mu, sv, a1.w);
            } else {
                a0.x = fmaf(v0.x, sv, a0.x); a0.y = fmaf(v0.y, sv, a0.y);
                a0.z = fmaf(v0.z, sv, a0.z); a0.w = fmaf(v0.w, sv, a0.w);
                a1.x = fmaf(v1.x, sv, a1.x); a1.y = fmaf(v1.y, sv, a1.y);
                a1.z = fmaf(v1.z, sv, a1.z); a1.w = fmaf(v1.w, sv, a1.w);
            }
        }
    }
    float nd = g_norm_d[gw];
    a0.x *= nd; a0.y *= nd; a0.z *= nd; a0.w *= nd;
    a1.x *= nd; a1.y *= nd; a1.z *= nd; a1.w *= nd;
    float4* o4 = reinterpret_cast<float4*>(out);
    o4[(size_t)gw * (FDIM / 4) + lane]      = a0;
    o4[(size_t)gw * (FDIM / 4) + 32 + lane] = a1;
}

// ---------------- SpMM 64-wide (final layer, with bias) ----------------
__global__ void k_spmm64(const float* __restrict__ tin, const float* __restrict__ bias,
                         float* __restrict__ out) {
    int gw = (blockIdx.x * blockDim.x + threadIdx.x) >> 5;
    int lane = threadIdx.x & 31;
    if (gw >= NN_NODES) return;

    int s0 = g_row_off[gw], s1 = g_row_off[gw + 1];
    float2 a = make_float2(0.f, 0.f);
    const float2* __restrict__ t2 = reinterpret_cast<const float2*>(tin);

    for (int base = s0; base < s1; base += 32) {
        int kk = base + lane;
        int j = 0; float sc = 0.f;
        if (kk < s1) { j = g_col[kk]; sc = g_norm_s[j]; }
        int cnt = min(32, s1 - base);
#pragma unroll 4
        for (int i = 0; i < cnt; i++) {
            int   jj = __shfl_sync(0xffffffffu, j, i);
            float sj = __shfl_sync(0xffffffffu, sc, i);
            float2 v = t2[(size_t)jj * (CDIM / 2) + lane];
            a.x = fmaf(v.x, sj, a.x);
            a.y = fmaf(v.y, sj, a.y);
        }
    }
    float nd = g_norm_d[gw];
    float2 b = reinterpret_cast<const float2*>(bias)[lane];
    float2 o;
    o.x = fmaf(a.x, nd, b.x);
    o.y = fmaf(a.y, nd, b.y);
    reinterpret_cast<float2*>(out)[(size_t)gw * (CDIM / 2) + lane] = o;
}

// ---------------- TF32 tensor-core GEMM ----------------
// C[M,Nn] = op(A[M,K]) @ B[K,Nn]  via mma.sync.m16n8k8.tf32
// epilogue: optional +bias, relu, double sum/sumsq stats
__device__ __forceinline__ unsigned f2tf32(float x) {
    unsigned r;
    asm("cvt.rna.tf32.f32 %0, %1;" : "=r"(r) : "f"(x));
    return r;
}

template <int BM, int BN, int WM, int WN, bool BIAS_RELU, bool STATS, bool LNA>
__global__ void k_gemm_tf32(const float* __restrict__ A, const float* __restrict__ B,
                            const float* __restrict__ bias, float* __restrict__ C,
                            int M, int Nn, int K) {
    constexpr int BK = 32;
    constexpr int LDA = BK + 8;          // 40: float4-aligned rows
    constexpr int LDB = BN + 8;          // conflict-free B frag reads
    constexpr int NWARP = (BM / WM) * (BN / WN);
    constexpr int NT = NWARP * 32;
    constexpr int MFRAG = WM / 16;
    constexpr int NFRAG = WN / 8;

    __shared__ float As[BM * LDA];
    __shared__ float Bs[BK * LDB];

    const int tid  = threadIdx.x;
    const int lane = tid & 31;
    const int warp = tid >> 5;
    const int wm0 = (warp / (BN / WN)) * WM;
    const int wn0 = (warp % (BN / WN)) * WN;
    const int bm0 = blockIdx.x * BM;
    const int bn0 = blockIdx.y * BN;

    float mu = 0.f, inv = 1.f;
    if (LNA) { mu = g_ln[0]; inv = g_ln[1]; }

    float acc[MFRAG][NFRAG][4];
#pragma unroll
    for (int i = 0; i < MFRAG; i++)
#pragma unroll
        for (int j = 0; j < NFRAG; j++)
#pragma unroll
            for (int q = 0; q < 4; q++) acc[i][j][q] = 0.f;

    const int gr = lane >> 2;   // group row (0..7)
    const int gc = lane & 3;    // group col (0..3)

    for (int k0 = 0; k0 < K; k0 += BK) {
        // stage A (LN + tf32 convert)
#pragma unroll
        for (int p = 0; p < (BM * BK / 4) / NT; p++) {
            int idx = tid + p * NT;
            int m = idx / (BK / 4), q = idx % (BK / 4);
            int row = bm0 + m;
            float4 v = make_float4(0.f, 0.f, 0.f, 0.f);
            if (row < M)
                v = *reinterpret_cast<const float4*>(&A[(size_t)row * K + k0 + q * 4]);
            if (LNA) {
                v.x = (v.x - mu) * inv; v.y = (v.y - mu) * inv;
                v.z = (v.z - mu) * inv; v.w = (v.w - mu) * inv;
            }
            float4 t;
            t.x = __uint_as_float(f2tf32(v.x));
            t.y = __uint_as_float(f2tf32(v.y));
            t.z = __uint_as_float(f2tf32(v.z));
            t.w = __uint_as_float(f2tf32(v.w));
            *reinterpret_cast<float4*>(&As[m * LDA + q * 4]) = t;
        }
        // stage B (tf32 convert)
#pragma unroll
        for (int p = 0; p < (BK * BN / 4) / NT; p++) {
            int idx = tid + p * NT;
            int k = idx / (BN / 4), n4 = idx % (BN / 4);
            float4 v = *reinterpret_cast<const float4*>(&B[(size_t)(k0 + k) * Nn + bn0 + n4 * 4]);
            float4 t;
            t.x = __uint_as_float(f2tf32(v.x));
            t.y = __uint_as_float(f2tf32(v.y));
            t.z = __uint_as_float(f2tf32(v.z));
            t.w = __uint_as_float(f2tf32(v.w));
            *reinterpret_cast<float4*>(&Bs[k * LDB + n4 * 4]) = t;
        }
        __syncthreads();

#pragma unroll
        for (int ks = 0; ks < BK / 8; ks++) {
            const int kb = ks * 8;
            unsigned a[MFRAG][4];
#pragma unroll
            for (int mi = 0; mi < MFRAG; mi++) {
                int r = wm0 + mi * 16 + gr;
                a[mi][0] = __float_as_uint(As[r * LDA + kb + gc]);
                a[mi][1] = __float_as_uint(As[(r + 8) * LDA + kb + gc]);
                a[mi][2] = __float_as_uint(As[r * LDA + kb + gc + 4]);
                a[mi][3] = __float_as_uint(As[(r + 8) * LDA + kb + gc + 4]);
            }
            unsigned b[NFRAG][2];
#pragma unroll
            for (int ni = 0; ni < NFRAG; ni++) {
                int c = wn0 + ni * 8 + gr;
                b[ni][0] = __float_as_uint(Bs[(kb + gc) * LDB + c]);
                b[ni][1] = __float_as_uint(Bs[(kb + gc + 4) * LDB + c]);
            }
#pragma unroll
            for (int mi = 0; mi < MFRAG; mi++)
#pragma unroll
                for (int ni = 0; ni < NFRAG; ni++) {
                    asm volatile(
                        "mma.sync.aligned.m16n8k8.row.col.f32.tf32.tf32.f32 "
                        "{%0,%1,%2,%3}, {%4,%5,%6,%7}, {%8,%9}, {%0,%1,%2,%3};"
                        : "+f"(acc[mi][ni][0]), "+f"(acc[mi][ni][1]),
                          "+f"(acc[mi][ni][2]), "+f"(acc[mi][ni][3])
                        : "r"(a[mi][0]), "r"(a[mi][1]), "r"(a[mi][2]), "r"(a[mi][3]),
                          "r"(b[ni][0]), "r"(b[ni][1]));
                }
        }
        __syncthreads();
    }

    // epilogue: bias+relu, store, stats
    double psum = 0.0, psq = 0.0;
#pragma unroll
    for (int mi = 0; mi < MFRAG; mi++) {
#pragma unroll
        for (int ni = 0; ni < NFRAG; ni++) {
            int c0 = bn0 + wn0 + ni * 8 + gc * 2;
            float2 bb = make_float2(0.f, 0.f);
            if (BIAS_RELU) bb = *reinterpret_cast<const float2*>(&bias[c0]);
#pragma unroll
            for (int half = 0; half < 2; half++) {
                int row = bm0 + wm0 + mi * 16 + gr + half * 8;
                if (row >= M) continue;
                float x = acc[mi][ni][half * 2 + 0];
                float y = acc[mi][ni][half * 2 + 1];
                if (BIAS_RELU) {
                    x = fmaxf(x + bb.x, 0.f);
                    y = fmaxf(y + bb.y, 0.f);
                }
                *reinterpret_cast<float2*>(&C[(size_t)row * Nn + c0]) = make_float2(x, y);
                if (STATS) {
                    psum += (double)x + (double)y;
                    psq  += (double)x * x + (double)y * y;
                }
            }
        }
    }

    if (STATS) {
#pragma unroll
        for (int off = 16; off > 0; off >>= 1) {
            psum += __shfl_down_sync(0xffffffffu, psum, off);
            psq  += __shfl_down_sync(0xffffffffu, psq, off);
        }
        if (lane == 0) {
            atomicAdd(&g_stats[0], psum);
            atomicAdd(&g_stats[1], psq);
        }
    }
}

__global__ void k_finalize(double count) {
    double s = g_stats[0], ss = g_stats[1];
    double mu = s / count;
    double var = ss / count - mu * mu;
    g_ln[0] = (float)mu;
    g_ln[1] = (float)(1.0 / sqrt(var + (double)LN_EPS));
    g_stats[0] = 0.0;
    g_stats[1] = 0.0;
}

// ---------------- launch ----------------
extern "C" void kernel_launch(void* const* d_in, const int* in_sizes, int n_in,
                              void* d_out, int out_size) {
    const float* feat = (const float*)d_in[0];
    const int*   src  = (const int*)d_in[1];
    const int*   dst  = (const int*)d_in[2];
    const float* W0   = (const float*)d_in[3];
    const float* b0   = (const float*)d_in[4];
    const float* W1   = (const float*)d_in[5];
    const float* b1   = (const float*)d_in[6];
    const float* W2   = (const float*)d_in[7];
    const float* b2   = (const float*)d_in[8];
    float* out = (float*)d_out;

    float *agg = nullptr, *hbuf = nullptr;
    cudaGetSymbolAddress((void**)&agg, g_agg);
    cudaGetSymbolAddress((void**)&hbuf, g_h);

    const int NB_N = (NN_NODES + 255) / 256;
    const int NB_E = (EE_EDGES + 255) / 256;
    const int NB_W = (NN_NODES * 32 + 255) / 256;  // warp per row

    // setup: degrees, norms, CSR (by dst)
    k_init<<<NB_N, 256>>>();
    k_degrees<<<NB_E, 256>>>(src, dst);
    k_scan<<<1, 1024>>>();
    k_fill<<<NB_E, 256>>>(src, dst);

    const int GM = (NN_NODES + 127) / 128;
    const double cnt = (double)NN_NODES * FDIM;

    // layer 1: agg = DAD*X ; h1 = relu(agg@W0 + b0) (+stats)
    k_spmm256<false><<<NB_W, 256>>>(feat, agg);
    k_gemm_tf32<128, 128, 64, 32, true, true, false>
        <<<dim3(GM, FDIM / 128), 256>>>(agg, W0, b0, hbuf, NN_NODES, FDIM, FDIM);
    k_finalize<<<1, 1>>>(cnt);

    // layer 2: agg = DAD*LN(h1) ; h2 = relu(agg@W1 + b1) (+stats)
    k_spmm256<true><<<NB_W, 256>>>(hbuf, agg);
    k_gemm_tf32<128, 128, 64, 32, true, true, false>
        <<<dim3(GM, FDIM / 128), 256>>>(agg, W1, b1, hbuf, NN_NODES, FDIM, FDIM);
    k_finalize<<<1, 1>>>(cnt);

    // layer 3 (reordered): t = LN(h2)@W2 ; out = DAD*t + b2
    k_gemm_tf32<128, 64, 32, 32, false, false, true>
        <<<dim3(GM, 1), 256>>>(hbuf, W2, nullptr, agg, NN_NODES, CDIM, FDIM);
    k_spmm64<<<NB_W, 256>>>(agg, b2, out);
}